// round 7
// baseline (speedup 1.0000x reference)
#include <cuda_runtime.h>

// Problem constants
#define NQ   20
#define NL   8
#define BB   32
#define DIM  (1u << NQ)        // 1048576
#define NF4  (DIM / 4)         // 262144 float4s per statevector

// Fused geometry: 1024 blocks x 256 threads, 1 float4/thread/batch.
// Element i = f*4 + r,  f = c*256 + t.
//   qubits 0,1   <- r   (float4 lane)
//   qubits 2..9  <- t   (deferred via smem totals)
//   qubits 10..19<- c   (free, applied at write-out)
#define TPB   256
#define GRID  1024
#define HALF  16               // batches per smem half

// Scratch: [b][c][24] padded rows (21 used). 32*1024*24 floats = 3 MB.
__device__ float g_part[(size_t)BB * GRID * 24];

// ---------------------------------------------------------------------------
// Fused kernel: G slice in registers, sweep 32 batches in two 16-batch halves.
// ---------------------------------------------------------------------------
__global__ void __launch_bounds__(TPB, 7) k_fused(const float* __restrict__ noise,
                                                  const float* __restrict__ amps) {
    const int c    = blockIdx.x;
    const int t    = threadIdx.x;
    const int lane = t & 31, warp = t >> 5;

    const size_t base = (size_t)c * TPB + t;
    const float4* n4 = reinterpret_cast<const float4*>(noise);
    const float4* a4 = reinterpret_cast<const float4*>(amps);

    // ---- G slice (rolling product; tiny share of traffic) ----
    float4 G;
    {
        float4 v = __ldcs(n4 + base);
        G.x = v.x * v.x; G.y = v.y * v.y; G.z = v.z * v.z; G.w = v.w * v.w;
#pragma unroll
        for (int l = 1; l < NL; l++) {
            v = __ldcs(n4 + (size_t)l * NF4 + base);
            G.x *= v.x * v.x; G.y *= v.y * v.y;
            G.z *= v.z * v.z; G.w *= v.w * v.w;
        }
    }

    __shared__ float sT[HALF][TPB];        // per-thread totals, one half at a time
    __shared__ float red2[HALF][8][2];     // warp-reduced acc0, acc1

    for (int h = 0; h < 2; h++) {
        const float4* ap = a4 + (size_t)(h * HALF) * NF4 + base;

#pragma unroll 4
        for (int bb = 0; bb < HALF; bb++) {
            float4 a = __ldcs(ap);
            ap += NF4;
            float w0 = a.x * a.x * G.x;
            float w1 = a.y * a.y * G.y;
            float w2 = a.z * a.z * G.z;
            float w3 = a.w * a.w * G.w;
            float s    = (w0 + w1) + (w2 + w3);
            float acc0 = w1 + w3;                      // qubit 0
            float acc1 = w2 + w3;                      // qubit 1
#pragma unroll
            for (int o = 16; o > 0; o >>= 1) {
                acc0 += __shfl_xor_sync(0xffffffffu, acc0, o);
                acc1 += __shfl_xor_sync(0xffffffffu, acc1, o);
            }
            if (lane == 0) { red2[bb][warp][0] = acc0; red2[bb][warp][1] = acc1; }
            sT[bb][t] = s;
        }
        __syncthreads();

        // ---- combine: warp handles batches bb = warp*2 + {0,1} ----
#pragma unroll
        for (int e = 0; e < 2; e++) {
            const int bb = warp * 2 + e;
            const int b  = h * HALF + bb;
            float v[8];
#pragma unroll
            for (int k = 0; k < 8; k++) v[k] = sT[bb][lane + 32 * k];
            float tt  = ((v[0] + v[1]) + (v[2] + v[3])) + ((v[4] + v[5]) + (v[6] + v[7]));
            float m[8];
            m[5] = (v[1] + v[3]) + (v[5] + v[7]);      // t bit 5 -> qubit 7
            m[6] = (v[2] + v[3]) + (v[6] + v[7]);      // t bit 6 -> qubit 8
            m[7] = (v[4] + v[5]) + (v[6] + v[7]);      // t bit 7 -> qubit 9
#pragma unroll
            for (int j = 0; j < 5; j++)                // t bits 0..4 -> qubits 2..6
                m[j] = ((lane >> j) & 1) ? tt : 0.f;
#pragma unroll
            for (int o = 16; o > 0; o >>= 1) {
                tt += __shfl_xor_sync(0xffffffffu, tt, o);
#pragma unroll
                for (int j = 0; j < 8; j++)
                    m[j] += __shfl_xor_sync(0xffffffffu, m[j], o);
            }
            if (lane == 0) {
                float* dst = &g_part[((size_t)b * GRID + c) * 24];
                float q0 = 0.f, q1 = 0.f;
#pragma unroll
                for (int w = 0; w < 8; w++) { q0 += red2[bb][w][0]; q1 += red2[bb][w][1]; }
                dst[0] = q0;
                dst[1] = q1;
#pragma unroll
                for (int j = 0; j < 8; j++) dst[2 + j] = m[j];      // qubits 2..9
#pragma unroll
                for (int j = 0; j < 10; j++)                        // qubits 10..19 <- c bits
                    dst[10 + j] = ((c >> j) & 1) ? tt : 0.f;
                dst[20] = tt;
            }
        }
        __syncthreads();
    }
}

// ---------------------------------------------------------------------------
// Final kernel: block b reduces 1024 chunk rows, then tanh(qp @ Wi + bi).
// Rows are [b][c][24]: warp reads 32 consecutive 96B rows -> coalesced.
// ---------------------------------------------------------------------------
__global__ void __launch_bounds__(256) k_final(const float* __restrict__ Wi,
                                               const float* __restrict__ bi,
                                               float* __restrict__ out) {
    const int b = blockIdx.x;
    const int t = threadIdx.x;
    const int lane = t & 31, warp = t >> 5;

    float q[21];
#pragma unroll
    for (int k = 0; k < 21; k++) q[k] = 0.f;
#pragma unroll
    for (int j = 0; j < GRID / 256; j++) {
        const float* row = &g_part[((size_t)b * GRID + t + j * 256) * 24];
#pragma unroll
        for (int k = 0; k < 21; k++) q[k] += __ldg(row + k);
    }
#pragma unroll
    for (int k = 0; k < 21; k++) {
#pragma unroll
        for (int o = 16; o > 0; o >>= 1)
            q[k] += __shfl_xor_sync(0xffffffffu, q[k], o);
    }
    __shared__ float red[8][21];
    if (lane == 0) {
#pragma unroll
        for (int k = 0; k < 21; k++) red[warp][k] = q[k];
    }
    __syncthreads();
    __shared__ float Q[21];
    if (t < 21) {
        float s = 0.f;
#pragma unroll
        for (int w = 0; w < 8; w++) s += red[w][t];
        Q[t] = s;
    }
    __syncthreads();
    if (t < NQ) {
        const float inv = 1.f / Q[20];
        float acc = bi[t];
#pragma unroll
        for (int qq = 0; qq < NQ; qq++) acc += (Q[qq] * inv) * Wi[qq * NQ + t];
        out[b * NQ + t] = tanhf(acc);
    }
}

// ---------------------------------------------------------------------------
// Launch: 2 graph-capturable kernels, no syncs, no allocations.
// ---------------------------------------------------------------------------
extern "C" void kernel_launch(void* const* d_in, const int* in_sizes, int n_in,
                              void* d_out, int out_size) {
    int i_amps = 7, i_noise = 8, i_Wi = 9, i_bi = 10;
    for (int i = 0; i < n_in; i++) {
        const long sz = in_sizes[i];
        if (sz == (long)BB * (long)DIM)      i_amps  = i;  // 33,554,432
        else if (sz == (long)NL * (long)DIM) i_noise = i;  //  8,388,608
        else if (sz == NQ * NQ)              i_Wi    = i;  // 400
        else if (sz == NQ)                   i_bi    = i;  // 20
    }

    const float* noise = (const float*)d_in[i_noise];
    const float* amps  = (const float*)d_in[i_amps];
    const float* Wi    = (const float*)d_in[i_Wi];
    const float* bi    = (const float*)d_in[i_bi];
    float* out         = (float*)d_out;

    k_fused<<<GRID, TPB>>>(noise, amps);   // 1024 blocks, 56 warps/SM, one wave
    k_final<<<BB, 256>>>(Wi, bi, out);     // 32 blocks, coalesced rows
}

// round 8
// speedup vs baseline: 1.1568x; 1.1568x over previous
#include <cuda_runtime.h>

// Problem constants
#define NQ   20
#define NL   8
#define BB   32
#define DIM  (1u << NQ)        // 1048576
#define NF4  (DIM / 4)         // 262144 float4s per statevector
#define TPB  256

// K2 geometry (R3, measured best): 32 chunks x 16 batch-groups = 512 blocks
#define CHUNKS 32
#define BPG 2
#define NGRP (BB / BPG)                // 16
#define F4_PER_CHUNK (NF4 / CHUNKS)    // 8192
#define NIT 32                         // iterations; NIT*TPB == F4_PER_CHUNK
#define NSLOT 4                        // smem ring slots
#define DEPTH 3                        // outstanding commit groups

// Scratch
__device__ float g_G[DIM];
__device__ float g_part[CHUNKS * NGRP * BPG * 21];

// cp.async helpers (register-free async copies -> true deep MLP)
__device__ __forceinline__ unsigned smem_u32(const void* p) {
    return (unsigned)__cvta_generic_to_shared(p);
}
#define CP16(smem_addr, gptr)                                               \
    asm volatile("cp.async.cg.shared.global [%0], [%1], 16;"                \
                 :: "r"(smem_addr), "l"(gptr) : "memory")
#define CP_COMMIT()  asm volatile("cp.async.commit_group;" ::: "memory")
#define CP_WAIT(n)   asm volatile("cp.async.wait_group %0;" :: "n"(n) : "memory")

// ---------------------------------------------------------------------------
// Kernel 1: G[i] = prod_l noise[l,i]^2.
// 8 cp.async per thread (no dst registers) -> guaranteed MLP=8.
// Each thread reads back only its own smem slots: no __syncthreads needed.
// ---------------------------------------------------------------------------
__global__ void __launch_bounds__(TPB) k_prodG(const float* __restrict__ noise) {
    __shared__ float4 buf[NL][TPB];                 // 32 KB
    const unsigned i = blockIdx.x * TPB + threadIdx.x;
    const int t = threadIdx.x;
    const float4* n4 = reinterpret_cast<const float4*>(noise);

#pragma unroll
    for (int l = 0; l < NL; l++)
        CP16(smem_u32(&buf[l][t]), n4 + (size_t)l * NF4 + i);
    CP_COMMIT();
    CP_WAIT(0);

    float4 v0 = buf[0][t], v1 = buf[1][t], v2 = buf[2][t], v3 = buf[3][t];
    float4 v4 = buf[4][t], v5 = buf[5][t], v6 = buf[6][t], v7 = buf[7][t];
    float4 g;
    g.x = ((v0.x*v0.x)*(v1.x*v1.x)) * ((v2.x*v2.x)*(v3.x*v3.x))
        * (((v4.x*v4.x)*(v5.x*v5.x)) * ((v6.x*v6.x)*(v7.x*v7.x)));
    g.y = ((v0.y*v0.y)*(v1.y*v1.y)) * ((v2.y*v2.y)*(v3.y*v3.y))
        * (((v4.y*v4.y)*(v5.y*v5.y)) * ((v6.y*v6.y)*(v7.y*v7.y)));
    g.z = ((v0.z*v0.z)*(v1.z*v1.z)) * ((v2.z*v2.z)*(v3.z*v3.z))
        * (((v4.z*v4.z)*(v5.z*v5.z)) * ((v6.z*v6.z)*(v7.z*v7.z)));
    g.w = ((v0.w*v0.w)*(v1.w*v1.w)) * ((v2.w*v2.w)*(v3.w*v3.w))
        * (((v4.w*v4.w)*(v5.w*v5.w)) * ((v6.w*v6.w)*(v7.w*v7.w)));
    reinterpret_cast<float4*>(g_G)[i] = g;
}

// ---------------------------------------------------------------------------
// Kernel 2: bit-masked reduction (R3 geometry) with per-thread cp.async
// pipeline on the amps streams. Thread t only ever touches smem word [.][.][t]
// -> no __syncthreads in the pipeline; slot reuse lags consumption by one
// full iteration (NSLOT = DEPTH + 1).
// Element index i = idx*4 + r;  idx = chunk*8192 + j*256 + t.
//   qubits 0,1   <- r       qubits 2..9  <- t bits (at reduction)
//   qubits 10..13<- j&15    qubit 14     <- j>>4
//   qubits 15..19<- chunk bits (at reduction)
// ---------------------------------------------------------------------------
__global__ void __launch_bounds__(TPB) k_bitsum(const float* __restrict__ amps) {
    __shared__ float4 bufA[2][NSLOT][TPB];          // 32 KB
    const int bg    = blockIdx.x & (NGRP - 1);
    const int chunk = blockIdx.x >> 4;
    const int t     = threadIdx.x;

    const size_t sliceOff = (size_t)chunk * F4_PER_CHUNK + t;
    const float4* g4   = reinterpret_cast<const float4*>(g_G) + sliceOff;
    const float4* a4_0 = reinterpret_cast<const float4*>(amps)
                         + (size_t)(bg * BPG + 0) * NF4 + sliceOff;
    const float4* a4_1 = reinterpret_cast<const float4*>(amps)
                         + (size_t)(bg * BPG + 1) * NF4 + sliceOff;

    // prologue: fill DEPTH stages
#pragma unroll
    for (int d = 0; d < DEPTH; d++) {
        CP16(smem_u32(&bufA[0][d][t]), a4_0 + d * TPB);
        CP16(smem_u32(&bufA[1][d][t]), a4_1 + d * TPB);
        CP_COMMIT();
    }

    float acc0[BPG]  = {0.f, 0.f}, acc1[BPG]  = {0.f, 0.f};
    float accJ0[BPG] = {0.f, 0.f}, accJ1[BPG] = {0.f, 0.f};
    float accJ2[BPG] = {0.f, 0.f}, accJ3[BPG] = {0.f, 0.f};
    float accO[BPG]  = {0.f, 0.f}, accT[BPG]  = {0.f, 0.f};

#pragma unroll
    for (int j = 0; j < NIT; j++) {
        CP_WAIT(DEPTH - 1);                         // stage j resident
        float4 g  = __ldg(g4 + j * TPB);            // L2-hot, shared by 16 blocks
        float4 a0 = bufA[0][j & (NSLOT - 1)][t];    // LDS.128
        float4 a1 = bufA[1][j & (NSLOT - 1)][t];
        if (j + DEPTH < NIT) {                      // refill slot consumed at j-1
            const int off = (j + DEPTH) * TPB;
            const int sl  = (j + DEPTH) & (NSLOT - 1);
            CP16(smem_u32(&bufA[0][sl][t]), a4_0 + off);
            CP16(smem_u32(&bufA[1][sl][t]), a4_1 + off);
            CP_COMMIT();
        }
#pragma unroll
        for (int b2 = 0; b2 < BPG; b2++) {
            float4 a = b2 ? a1 : a0;
            float w0 = a.x * a.x * g.x;
            float w1 = a.y * a.y * g.y;
            float w2 = a.z * a.z * g.z;
            float w3 = a.w * a.w * g.w;
            float s  = (w0 + w1) + (w2 + w3);
            acc0[b2] += w1 + w3;               // qubit 0
            acc1[b2] += w2 + w3;               // qubit 1
            if (j & 1)  accJ0[b2] += s;        // qubit 10 (compile-time)
            if (j & 2)  accJ1[b2] += s;        // qubit 11
            if (j & 4)  accJ2[b2] += s;        // qubit 12
            if (j & 8)  accJ3[b2] += s;        // qubit 13
            if (j & 16) accO[b2]  += s;        // qubit 14
            accT[b2] += s;
        }
    }

    __shared__ float red[TPB / 32][BPG][21];
    const int wid = t >> 5, lane = t & 31;

#pragma unroll
    for (int b2 = 0; b2 < BPG; b2++) {
        float vals[21];
        vals[0] = acc0[b2];
        vals[1] = acc1[b2];
#pragma unroll
        for (int k = 0; k < 8; k++) vals[2 + k] = ((t >> k) & 1) ? accT[b2] : 0.f;
        vals[10] = accJ0[b2]; vals[11] = accJ1[b2];
        vals[12] = accJ2[b2]; vals[13] = accJ3[b2];
        vals[14] = accO[b2];
#pragma unroll
        for (int m = 0; m < 5; m++) vals[15 + m] = ((chunk >> m) & 1) ? accT[b2] : 0.f;
        vals[20] = accT[b2];
#pragma unroll
        for (int k = 0; k < 21; k++) {
#pragma unroll
            for (int o = 16; o > 0; o >>= 1)
                vals[k] += __shfl_xor_sync(0xffffffffu, vals[k], o);
        }
        if (lane == 0) {
#pragma unroll
            for (int k = 0; k < 21; k++) red[wid][b2][k] = vals[k];
        }
    }
    __syncthreads();
    if (t < BPG * 21) {
        const int b2 = t / 21, k = t % 21;
        float s = 0.f;
#pragma unroll
        for (int w = 0; w < TPB / 32; w++) s += red[w][b2][k];
        g_part[(size_t)blockIdx.x * (BPG * 21) + t] = s;
    }
}

// ---------------------------------------------------------------------------
// Kernel 3: reduce partials -> qubit probs -> tanh(qp @ Wi + bi)
// ---------------------------------------------------------------------------
__global__ void k_final(const float* __restrict__ Wi, const float* __restrict__ bi,
                        float* __restrict__ out) {
    __shared__ float Q[BB][21];
    const int t = threadIdx.x;
    if (t < BB * 21) {
        const int b = t / 21, k = t % 21;
        const int bg = b >> 1, b2 = b & 1;
        float s = 0.f;
#pragma unroll
        for (int c = 0; c < CHUNKS; c++)
            s += g_part[(size_t)(c * NGRP + bg) * (BPG * 21) + b2 * 21 + k];
        Q[b][k] = s;
    }
    __syncthreads();
    if (t < BB * NQ) {
        const int b = t / NQ, j = t % NQ;
        const float inv = 1.f / Q[b][20];
        float acc = bi[j];
#pragma unroll
        for (int q = 0; q < NQ; q++) acc += (Q[b][q] * inv) * Wi[q * NQ + j];
        out[t] = tanhf(acc);
    }
}

// ---------------------------------------------------------------------------
// Launch
// ---------------------------------------------------------------------------
extern "C" void kernel_launch(void* const* d_in, const int* in_sizes, int n_in,
                              void* d_out, int out_size) {
    int i_amps = 7, i_noise = 8, i_Wi = 9, i_bi = 10;
    for (int i = 0; i < n_in; i++) {
        const long sz = in_sizes[i];
        if (sz == (long)BB * (long)DIM)      i_amps  = i;
        else if (sz == (long)NL * (long)DIM) i_noise = i;
        else if (sz == NQ * NQ)              i_Wi    = i;
        else if (sz == NQ)                   i_bi    = i;
    }

    const float* noise = (const float*)d_in[i_noise];
    const float* amps  = (const float*)d_in[i_amps];
    const float* Wi    = (const float*)d_in[i_Wi];
    const float* bi    = (const float*)d_in[i_bi];
    float* out         = (float*)d_out;

    k_prodG <<<NF4 / TPB, TPB>>>(noise);        // 1024 blocks, cp.async MLP=8
    k_bitsum<<<CHUNKS * NGRP, TPB>>>(amps);     //  512 blocks, cp.async pipeline
    k_final <<<1, BB * 21>>>(Wi, bi, out);
}